// round 2
// baseline (speedup 1.0000x reference)
#include <cuda_runtime.h>
#include <cuda_bf16.h>

// scatter_mean: out[m, c] = sum_{i: idx[i]==m} in[i, c] / max(count_m, 1)
// N = 4,000,000 rows, C = 16 channels fp32, M = 500,000 segments.
// NOTE: reference asks for int64 indices, but JAX x64 is disabled by default,
// so unq_inv arrives as int32. Read as const int*.

#define CHANNELS 16
#define MAX_SEGMENTS 500000

// Scratch: per-segment counts (allocation-free rule -> __device__ global).
__device__ float g_counts[MAX_SEGMENTS];

// ---------------------------------------------------------------------------
// Kernel 1: zero the output sums and the counts scratch.
// ---------------------------------------------------------------------------
__global__ void dve_zero_kernel(float4* __restrict__ out, int out_n4, int m) {
    int stride = gridDim.x * blockDim.x;
    float4 z = make_float4(0.f, 0.f, 0.f, 0.f);
    for (int j = blockIdx.x * blockDim.x + threadIdx.x; j < out_n4; j += stride)
        out[j] = z;
    for (int j = blockIdx.x * blockDim.x + threadIdx.x; j < m; j += stride)
        g_counts[j] = 0.0f;
}

// ---------------------------------------------------------------------------
// Kernel 2: scatter-add. One thread per input row.
// 4x float4 loads + 4x red.global.add.v4.f32 + 1 count RED per row.
// Sums+counts region (34 MB) fits in the 126 MB L2 -> atomics resolve in L2.
// ---------------------------------------------------------------------------
__global__ void dve_scatter_kernel(const float4* __restrict__ in,
                                   const int* __restrict__ idx,
                                   float* __restrict__ sums,
                                   int n) {
    int i = blockIdx.x * blockDim.x + threadIdx.x;
    if (i >= n) return;

    int s = idx[i];

    const float4* row = in + (size_t)i * 4;
    float4 a = __ldg(row + 0);
    float4 b = __ldg(row + 1);
    float4 c = __ldg(row + 2);
    float4 d = __ldg(row + 3);

    float* p = sums + (size_t)s * CHANNELS;  // 64B-aligned (16 floats/row)

    asm volatile("red.global.add.v4.f32 [%0], {%1, %2, %3, %4};"
                 :: "l"(p + 0), "f"(a.x), "f"(a.y), "f"(a.z), "f"(a.w) : "memory");
    asm volatile("red.global.add.v4.f32 [%0], {%1, %2, %3, %4};"
                 :: "l"(p + 4), "f"(b.x), "f"(b.y), "f"(b.z), "f"(b.w) : "memory");
    asm volatile("red.global.add.v4.f32 [%0], {%1, %2, %3, %4};"
                 :: "l"(p + 8), "f"(c.x), "f"(c.y), "f"(c.z), "f"(c.w) : "memory");
    asm volatile("red.global.add.v4.f32 [%0], {%1, %2, %3, %4};"
                 :: "l"(p + 12), "f"(d.x), "f"(d.y), "f"(d.z), "f"(d.w) : "memory");

    atomicAdd(&g_counts[s], 1.0f);
}

// ---------------------------------------------------------------------------
// Kernel 3: divide sums by max(count, 1). One thread per segment, in place.
// ---------------------------------------------------------------------------
__global__ void dve_finalize_kernel(float4* __restrict__ out, int m) {
    int i = blockIdx.x * blockDim.x + threadIdx.x;
    if (i >= m) return;

    float cnt = g_counts[i];
    float inv = 1.0f / fmaxf(cnt, 1.0f);

    float4* row = out + (size_t)i * 4;
#pragma unroll
    for (int k = 0; k < 4; k++) {
        float4 v = row[k];
        v.x *= inv; v.y *= inv; v.z *= inv; v.w *= inv;
        row[k] = v;
    }
}

// ---------------------------------------------------------------------------
// Launch
// ---------------------------------------------------------------------------
extern "C" void kernel_launch(void* const* d_in, const int* in_sizes, int n_in,
                              void* d_out, int out_size) {
    const float4* in = (const float4*)d_in[0];   // [N, 16] fp32
    const int* idx = (const int*)d_in[1];        // [N] int32 (JAX x64 off)
    float* out = (float*)d_out;                  // [M, 16] fp32

    int n = in_sizes[0] / CHANNELS;   // 4,000,000
    int m = out_size / CHANNELS;      // 500,000

    {
        int threads = 256;
        int blocks = 2048;  // grid-stride zero of 2M float4 + 0.5M floats
        dve_zero_kernel<<<blocks, threads>>>((float4*)d_out, out_size / 4, m);
    }
    {
        int threads = 256;
        int blocks = (n + threads - 1) / threads;
        dve_scatter_kernel<<<blocks, threads>>>(in, idx, out, n);
    }
    {
        int threads = 256;
        int blocks = (m + threads - 1) / threads;
        dve_finalize_kernel<<<blocks, threads>>>((float4*)d_out, m);
    }
}

// round 3
// speedup vs baseline: 1.3260x; 1.3260x over previous
#include <cuda_runtime.h>
#include <cuda_bf16.h>

// scatter_mean: out[m, c] = sum_{i: idx[i]==m} in[i, c] / max(count_m, 1)
// N = 4,000,000 rows, C = 16 channels fp32, M = 500,000 segments, idx int32.

#define CHANNELS 16
#define MAX_SEGMENTS 500000

// Scratch: per-segment counts (allocation-free rule -> __device__ global).
__device__ float g_counts[MAX_SEGMENTS];

// ---------------------------------------------------------------------------
// Kernel 1: zero the output sums and the counts scratch.
// ---------------------------------------------------------------------------
__global__ void dve_zero_kernel(float4* __restrict__ out, int out_n4, int m) {
    int stride = gridDim.x * blockDim.x;
    float4 z = make_float4(0.f, 0.f, 0.f, 0.f);
    for (int j = blockIdx.x * blockDim.x + threadIdx.x; j < out_n4; j += stride)
        out[j] = z;
    for (int j = blockIdx.x * blockDim.x + threadIdx.x; j < m; j += stride)
        g_counts[j] = 0.0f;
}

// ---------------------------------------------------------------------------
// Kernel 2: scatter-add, 4 lanes per row (quad-per-row).
// Each lane: 1 float4 load + 1 red.global.add.v4.f32. The 4 lanes of a quad
// hit consecutive 16B chunks of the same 64B destination row, so the L1tex
// coalescer merges each quad into ONE atomic wavefront (4x fewer L2 atomic
// requests than one-thread-per-row). Lane 0 of each quad adds the count.
// ---------------------------------------------------------------------------
__global__ void dve_scatter_kernel(const float4* __restrict__ in,
                                   const int* __restrict__ idx,
                                   float4* __restrict__ sums4,
                                   int n) {
    int t = blockIdx.x * blockDim.x + threadIdx.x;   // [0, 4n)
    int row = t >> 2;
    int q = t & 3;
    if (row >= n) return;

    int s = idx[row];                                 // quad-replicated, L1-dedup
    float4 v = __ldg(in + (size_t)row * 4 + q);       // warp reads 8 rows = 512B contiguous

    float4* p = sums4 + (size_t)s * 4 + q;            // quad covers one 64B row
    asm volatile("red.global.add.v4.f32 [%0], {%1, %2, %3, %4};"
                 :: "l"(p), "f"(v.x), "f"(v.y), "f"(v.z), "f"(v.w) : "memory");

    if (q == 0)
        atomicAdd(&g_counts[s], 1.0f);
}

// ---------------------------------------------------------------------------
// Kernel 3: divide sums by max(count, 1). One thread per segment, in place.
// ---------------------------------------------------------------------------
__global__ void dve_finalize_kernel(float4* __restrict__ out, int m) {
    int i = blockIdx.x * blockDim.x + threadIdx.x;
    if (i >= m) return;

    float cnt = g_counts[i];
    float inv = 1.0f / fmaxf(cnt, 1.0f);

    float4* row = out + (size_t)i * 4;
#pragma unroll
    for (int k = 0; k < 4; k++) {
        float4 v = row[k];
        v.x *= inv; v.y *= inv; v.z *= inv; v.w *= inv;
        row[k] = v;
    }
}

// ---------------------------------------------------------------------------
// Launch
// ---------------------------------------------------------------------------
extern "C" void kernel_launch(void* const* d_in, const int* in_sizes, int n_in,
                              void* d_out, int out_size) {
    const float4* in = (const float4*)d_in[0];   // [N, 16] fp32
    const int* idx = (const int*)d_in[1];        // [N] int32
    float* out = (float*)d_out;                  // [M, 16] fp32

    int n = in_sizes[0] / CHANNELS;   // 4,000,000
    int m = out_size / CHANNELS;      // 500,000

    {
        int threads = 256;
        int blocks = 2048;
        dve_zero_kernel<<<blocks, threads>>>((float4*)out, out_size / 4, m);
    }
    {
        int threads = 256;
        long long total = (long long)n * 4;
        int blocks = (int)((total + threads - 1) / threads);
        dve_scatter_kernel<<<blocks, threads>>>(in, idx, (float4*)out, n);
    }
    {
        int threads = 256;
        int blocks = (m + threads - 1) / threads;
        dve_finalize_kernel<<<blocks, threads>>>((float4*)out, m);
    }
}